// round 1
// baseline (speedup 1.0000x reference)
#include <cuda_runtime.h>
#include <math.h>

#define NPTS   500000
#define MCLUS  50000
#define DFEAT  128
#define AGG_W  132   // 131 used + 1 zero pad -> 16B-aligned rows

// Scratch (allocation-free: static device globals)
__device__ float g_agg[(size_t)MCLUS * AGG_W];   // ~26.4 MB
__device__ float g_h[(size_t)MCLUS * 128];       // ~25.6 MB

// ---------------- packed f32x2 helpers ----------------
__device__ __forceinline__ unsigned long long pack2(float lo, float hi) {
    unsigned long long r;
    asm("mov.b64 %0, {%1,%2};" : "=l"(r) : "f"(lo), "f"(hi));
    return r;
}
__device__ __forceinline__ unsigned long long fma2(unsigned long long a,
                                                   unsigned long long b,
                                                   unsigned long long c) {
    unsigned long long d;
    asm("fma.rn.f32x2 %0, %1, %2, %3;" : "=l"(d) : "l"(a), "l"(b), "l"(c));
    return d;
}
__device__ __forceinline__ float2 unpack2(unsigned long long v) {
    float2 f;
    asm("mov.b64 {%0,%1}, %2;" : "=f"(f.x), "=f"(f.y) : "l"(v));
    return f;
}
__device__ __forceinline__ void red4(float* addr, float a, float b, float c, float d) {
    asm volatile("red.global.add.v4.f32 [%0], {%1,%2,%3,%4};"
                 :: "l"(addr), "f"(a), "f"(b), "f"(c), "f"(d) : "memory");
}

// ---------------- kernel 0: zero agg ----------------
__global__ void zero_agg_kernel() {
    const size_t total4 = (size_t)MCLUS * AGG_W / 4;  // 1,650,000 float4
    float4* p = (float4*)g_agg;
    float4 z = make_float4(0.f, 0.f, 0.f, 0.f);
    for (size_t i = blockIdx.x * blockDim.x + threadIdx.x; i < total4;
         i += (size_t)gridDim.x * blockDim.x)
        p[i] = z;
}

// ---------------- kernel 1: attention MLP + weighted scatter ----------------
// One thread per point. 64 hidden units as 32 f32x2 accumulators.
// aW1 staged in smem as ulonglong2 (LDS.128 -> two packed f32x2 operands).
__global__ void __launch_bounds__(128) att_scatter_kernel(
    const float* __restrict__ feat, const float* __restrict__ pts,
    const float* __restrict__ ctr, const int* __restrict__ lab,
    const float* __restrict__ aW1, const float* __restrict__ ab1,
    const float* __restrict__ aW2, const float* __restrict__ ab2, int N)
{
    __shared__ ulonglong2 sW[131 * 16];   // w[k][0..63] -> 16 ulonglong2 per k
    __shared__ float sB1[64];
    __shared__ float sA2[64];
    __shared__ float sb2;

    const ulonglong2* w2 = (const ulonglong2*)aW1;  // 131*64 f32 = 2096 u128
    for (int idx = threadIdx.x; idx < 131 * 16; idx += 128) sW[idx] = w2[idx];
    if (threadIdx.x < 64) { sB1[threadIdx.x] = ab1[threadIdx.x]; sA2[threadIdx.x] = aW2[threadIdx.x]; }
    if (threadIdx.x == 0) sb2 = ab2[0];
    __syncthreads();

    int i = blockIdx.x * 128 + threadIdx.x;
    if (i >= N) return;

    int l = lab[i];
    float rx = ctr[l * 3 + 0] - pts[i * 3 + 0];
    float ry = ctr[l * 3 + 1] - pts[i * 3 + 1];
    float rz = ctr[l * 3 + 2] - pts[i * 3 + 2];

    unsigned long long acc[32];
#pragma unroll
    for (int j = 0; j < 32; j++) acc[j] = pack2(sB1[2 * j], sB1[2 * j + 1]);

    const float4* frow = (const float4*)(feat + (size_t)i * DFEAT);

#pragma unroll 1
    for (int kk = 0; kk < 32; kk++) {
        float4 tv = frow[kk];
        float te[4] = {tv.x, tv.y, tv.z, tv.w};
#pragma unroll
        for (int e = 0; e < 4; e++) {
            unsigned long long tp = pack2(te[e], te[e]);
            const ulonglong2* wr = &sW[(kk * 4 + e) * 16];
#pragma unroll
            for (int jj = 0; jj < 16; jj++) {
                ulonglong2 w = wr[jj];
                acc[2 * jj]     = fma2(tp, w.x, acc[2 * jj]);
                acc[2 * jj + 1] = fma2(tp, w.y, acc[2 * jj + 1]);
            }
        }
    }
    // rel-coord dims k = 128..130
    {
        float rel[3] = {rx, ry, rz};
#pragma unroll
        for (int e = 0; e < 3; e++) {
            unsigned long long tp = pack2(rel[e], rel[e]);
            const ulonglong2* wr = &sW[(128 + e) * 16];
#pragma unroll
            for (int jj = 0; jj < 16; jj++) {
                ulonglong2 w = wr[jj];
                acc[2 * jj]     = fma2(tp, w.x, acc[2 * jj]);
                acc[2 * jj + 1] = fma2(tp, w.y, acc[2 * jj + 1]);
            }
        }
    }

    // relu -> dot with aW2 -> sigmoid
    float s = sb2;
#pragma unroll
    for (int jj = 0; jj < 32; jj++) {
        float2 h = unpack2(acc[jj]);
        h.x = fmaxf(h.x, 0.f);
        h.y = fmaxf(h.y, 0.f);
        s += h.x * sA2[2 * jj] + h.y * sA2[2 * jj + 1];
    }
    float att = 1.f / (1.f + expf(-s));

    // scatter t*att into agg[label] with vector reductions (16B each)
    float* arow = g_agg + (size_t)l * AGG_W;
#pragma unroll 1
    for (int kk = 0; kk < 32; kk++) {
        float4 v = frow[kk];   // L1-resident from the MLP pass
        red4(arow + kk * 4, v.x * att, v.y * att, v.z * att, v.w * att);
    }
    red4(arow + 128, rx * att, ry * att, rz * att, 0.f);
}

// ---------------- kernel 2: h = relu(agg @ oW1 + ob1)  [50000 x 128] --------
// 2 threads per row, 64 outputs each (32 f32x2 accumulators).
__global__ void __launch_bounds__(256) gemmB_kernel(
    const float* __restrict__ oW1, const float* __restrict__ ob1)
{
    extern __shared__ ulonglong2 sW[];  // 132 rows x 32 entries = 4224 (67.6 KB)
    const ulonglong2* w2 = (const ulonglong2*)oW1;  // 131*128 f32 = 4192 u128
    for (int idx = threadIdx.x; idx < 4192; idx += 256) sW[idx] = w2[idx];
    for (int idx = 4192 + threadIdx.x; idx < 4224; idx += 256) {
        ulonglong2 z; z.x = 0ull; z.y = 0ull; sW[idx] = z;
    }
    __syncthreads();

    int g = blockIdx.x * 256 + threadIdx.x;
    int row = g >> 1;
    int half = g & 1;
    if (row >= MCLUS) return;

    unsigned long long acc[32];
#pragma unroll
    for (int jj = 0; jj < 32; jj++)
        acc[jj] = pack2(__ldg(ob1 + half * 64 + 2 * jj), __ldg(ob1 + half * 64 + 2 * jj + 1));

    const float4* arow = (const float4*)(g_agg + (size_t)row * AGG_W);
#pragma unroll 1
    for (int kk = 0; kk < 33; kk++) {         // 132 values (pad lane hits zero weights)
        float4 tv = arow[kk];
        float te[4] = {tv.x, tv.y, tv.z, tv.w};
#pragma unroll
        for (int e = 0; e < 4; e++) {
            unsigned long long tp = pack2(te[e], te[e]);
            const ulonglong2* wr = &sW[(kk * 4 + e) * 32 + half * 16];
#pragma unroll
            for (int jj = 0; jj < 16; jj++) {
                ulonglong2 w = wr[jj];
                acc[2 * jj]     = fma2(tp, w.x, acc[2 * jj]);
                acc[2 * jj + 1] = fma2(tp, w.y, acc[2 * jj + 1]);
            }
        }
    }

    float2* hrow = (float2*)(g_h + (size_t)row * 128 + half * 64);
#pragma unroll
    for (int jj = 0; jj < 32; jj++) {
        float2 v = unpack2(acc[jj]);
        v.x = fmaxf(v.x, 0.f);
        v.y = fmaxf(v.y, 0.f);
        hrow[jj] = v;
    }
}

// ---------------- kernel 3: out = relu(h @ oW2 + ob2)  [50000 x 256] --------
// 4 threads per row, 64 outputs each.
__global__ void __launch_bounds__(256) gemmC_kernel(
    const float* __restrict__ oW2, const float* __restrict__ ob2,
    float* __restrict__ out)
{
    extern __shared__ ulonglong2 sW[];  // 128 rows x 64 entries = 8192 (131 KB)
    const ulonglong2* w2 = (const ulonglong2*)oW2;  // 128*256 f32 = 8192 u128
    for (int idx = threadIdx.x; idx < 8192; idx += 256) sW[idx] = w2[idx];
    __syncthreads();

    int g = blockIdx.x * 256 + threadIdx.x;
    int row = g >> 2;
    int q = g & 3;
    if (row >= MCLUS) return;

    unsigned long long acc[32];
#pragma unroll
    for (int jj = 0; jj < 32; jj++)
        acc[jj] = pack2(__ldg(ob2 + q * 64 + 2 * jj), __ldg(ob2 + q * 64 + 2 * jj + 1));

    const float4* hrow = (const float4*)(g_h + (size_t)row * 128);
#pragma unroll 1
    for (int kk = 0; kk < 32; kk++) {
        float4 tv = hrow[kk];
        float te[4] = {tv.x, tv.y, tv.z, tv.w};
#pragma unroll
        for (int e = 0; e < 4; e++) {
            unsigned long long tp = pack2(te[e], te[e]);
            const ulonglong2* wr = &sW[(kk * 4 + e) * 64 + q * 16];
#pragma unroll
            for (int jj = 0; jj < 16; jj++) {
                ulonglong2 w = wr[jj];
                acc[2 * jj]     = fma2(tp, w.x, acc[2 * jj]);
                acc[2 * jj + 1] = fma2(tp, w.y, acc[2 * jj + 1]);
            }
        }
    }

    float2* orow = (float2*)(out + (size_t)row * 256 + q * 64);
#pragma unroll
    for (int jj = 0; jj < 32; jj++) {
        float2 v = unpack2(acc[jj]);
        v.x = fmaxf(v.x, 0.f);
        v.y = fmaxf(v.y, 0.f);
        orow[jj] = v;
    }
}

extern "C" void kernel_launch(void* const* d_in, const int* in_sizes, int n_in,
                              void* d_out, int out_size) {
    const float* feat = (const float*)d_in[0];
    const float* pts  = (const float*)d_in[1];
    const float* ctr  = (const float*)d_in[2];
    const int*   lab  = (const int*)d_in[3];
    const float* aW1  = (const float*)d_in[4];
    const float* ab1  = (const float*)d_in[5];
    const float* aW2  = (const float*)d_in[6];
    const float* ab2  = (const float*)d_in[7];
    const float* oW1  = (const float*)d_in[8];
    const float* ob1  = (const float*)d_in[9];
    const float* oW2  = (const float*)d_in[10];
    const float* ob2  = (const float*)d_in[11];
    float* out = (float*)d_out;

    cudaFuncSetAttribute(gemmB_kernel, cudaFuncAttributeMaxDynamicSharedMemorySize, 4224 * 16);
    cudaFuncSetAttribute(gemmC_kernel, cudaFuncAttributeMaxDynamicSharedMemorySize, 8192 * 16);

    zero_agg_kernel<<<1024, 256>>>();
    att_scatter_kernel<<<(NPTS + 127) / 128, 128>>>(feat, pts, ctr, lab,
                                                    aW1, ab1, aW2, ab2, NPTS);
    gemmB_kernel<<<(MCLUS * 2 + 255) / 256, 256, 4224 * 16>>>(oW1, ob1);
    gemmC_kernel<<<(MCLUS * 4 + 255) / 256, 256, 8192 * 16>>>(oW2, ob2, out);
}

// round 2
// speedup vs baseline: 2.6305x; 2.6305x over previous
#include <cuda_runtime.h>
#include <math.h>

#define NPTS   500000
#define MCLUS  50000

typedef unsigned long long u64;

__device__ float g_agg[(size_t)MCLUS * 132];   // 131 used + 1 pad
__device__ float g_h[(size_t)MCLUS * 128];

// dynamic smem (shared symbol across kernels)
extern __shared__ ulonglong2 dynW[];

// ---------------- packed f32x2 helpers ----------------
__device__ __forceinline__ u64 pack2(float lo, float hi) {
    u64 r;
    asm("mov.b64 %0, {%1,%2};" : "=l"(r) : "f"(lo), "f"(hi));
    return r;
}
__device__ __forceinline__ u64 fma2(u64 a, u64 b, u64 c) {
    u64 d;
    asm("fma.rn.f32x2 %0, %1, %2, %3;" : "=l"(d) : "l"(a), "l"(b), "l"(c));
    return d;
}
__device__ __forceinline__ float2 unpack2(u64 v) {
    float2 f;
    asm("mov.b64 {%0,%1}, %2;" : "=f"(f.x), "=f"(f.y) : "l"(v));
    return f;
}
__device__ __forceinline__ void red4(float* addr, float a, float b, float c, float d) {
    asm volatile("red.global.add.v4.f32 [%0], {%1,%2,%3,%4};"
                 :: "l"(addr), "f"(a), "f"(b), "f"(c), "f"(d) : "memory");
}

// ---------------- kernel 0: zero agg ----------------
__global__ void zero_agg_kernel() {
    const size_t total4 = (size_t)MCLUS * 132 / 4;
    float4* p = (float4*)g_agg;
    float4 z = make_float4(0.f, 0.f, 0.f, 0.f);
    for (size_t i = blockIdx.x * blockDim.x + threadIdx.x; i < total4;
         i += (size_t)gridDim.x * blockDim.x)
        p[i] = z;
}

// ============ kernel 1: attention MLP + weighted scatter ============
// 256 threads: cg = tid&3 (16 hidden cols), rg = tid>>2 (8 rows each) -> 512 rows/block
__global__ void __launch_bounds__(256) att_scatter_kernel(
    const float* __restrict__ feat, const float* __restrict__ pts,
    const float* __restrict__ ctr, const int* __restrict__ lab,
    const float* __restrict__ aW1, const float* __restrict__ ab1,
    const float* __restrict__ aW2, const float* __restrict__ ab2)
{
    __shared__ ulonglong2 sW[131 * 16];   // [k][q][cg] swizzled, 33.5KB
    __shared__ float sB1[64];
    __shared__ float sA2[64];
    __shared__ float sb2;

    {
        const ulonglong2* wsrc = (const ulonglong2*)aW1;   // 131*16 u128
        for (int idx = threadIdx.x; idx < 131 * 16; idx += 256) {
            int k = idx >> 4, rem = idx & 15;
            int c = rem >> 2, q = rem & 3;
            sW[k * 16 + q * 4 + c] = wsrc[idx];
        }
        if (threadIdx.x < 64) {
            sB1[threadIdx.x] = ab1[threadIdx.x];
            sA2[threadIdx.x] = aW2[threadIdx.x];
        }
        if (threadIdx.x == 0) sb2 = ab2[0];
    }
    __syncthreads();

    const int tid = threadIdx.x;
    const int cg = tid & 3;
    const int rg = tid >> 2;
    const long base = (long)blockIdx.x * 512 + (long)rg * 8;

    const float4* f4 = (const float4*)feat;
    int rowc[8];
#pragma unroll
    for (int r = 0; r < 8; r++) {
        long rr = base + r;
        rowc[r] = (rr < NPTS) ? (int)rr : (NPTS - 1);
    }

    // init acc with bias
    u64 acc[64];
    {
        const u64* b2 = (const u64*)sB1;
#pragma unroll
        for (int j = 0; j < 8; j++) {
            u64 bb = b2[cg * 8 + j];
#pragma unroll
            for (int r = 0; r < 8; r++) acc[r * 8 + j] = bb;
        }
    }
    // rel-coord dims k = 128..130 folded in up front
    {
        float rel[24];
#pragma unroll
        for (int r = 0; r < 8; r++) {
            int row = rowc[r];
            int l = lab[row];
            rel[r * 3 + 0] = ctr[l * 3 + 0] - pts[row * 3 + 0];
            rel[r * 3 + 1] = ctr[l * 3 + 1] - pts[row * 3 + 1];
            rel[r * 3 + 2] = ctr[l * 3 + 2] - pts[row * 3 + 2];
        }
#pragma unroll
        for (int e = 0; e < 3; e++) {
            const ulonglong2* wp = sW + (128 + e) * 16 + cg;
            ulonglong2 wa = wp[0], wb = wp[4], wc = wp[8], wd = wp[12];
            u64 wv[8] = {wa.x, wa.y, wb.x, wb.y, wc.x, wc.y, wd.x, wd.y};
#pragma unroll
            for (int r = 0; r < 8; r++) {
                u64 tp = pack2(rel[r * 3 + e], rel[r * 3 + e]);
#pragma unroll
                for (int j = 0; j < 8; j++)
                    acc[r * 8 + j] = fma2(tp, wv[j], acc[r * 8 + j]);
            }
        }
    }

    // main loop over 128 feature dims (32 float4 chunks) with prefetch
    float4 cur[8], nxt[8];
#pragma unroll
    for (int r = 0; r < 8; r++) cur[r] = f4[rowc[r] * 32];
#pragma unroll 1
    for (int kk = 0; kk < 32; kk++) {
        if (kk < 31) {
#pragma unroll
            for (int r = 0; r < 8; r++) nxt[r] = f4[rowc[r] * 32 + kk + 1];
        }
#pragma unroll
        for (int e = 0; e < 4; e++) {
            const ulonglong2* wp = sW + (kk * 4 + e) * 16 + cg;
            ulonglong2 wa = wp[0], wb = wp[4], wc = wp[8], wd = wp[12];
            u64 wv[8] = {wa.x, wa.y, wb.x, wb.y, wc.x, wc.y, wd.x, wd.y};
#pragma unroll
            for (int r = 0; r < 8; r++) {
                float4 c4 = cur[r];
                float ae = (e == 0) ? c4.x : (e == 1) ? c4.y : (e == 2) ? c4.z : c4.w;
                u64 tp = pack2(ae, ae);
#pragma unroll
                for (int j = 0; j < 8; j++)
                    acc[r * 8 + j] = fma2(tp, wv[j], acc[r * 8 + j]);
            }
        }
#pragma unroll
        for (int r = 0; r < 8; r++) cur[r] = nxt[r];
    }

    // relu + partial dot with aW2, reduce across 4 colgroup lanes
    float s[8];
#pragma unroll
    for (int r = 0; r < 8; r++) s[r] = 0.f;
#pragma unroll
    for (int j = 0; j < 8; j++) {
        float w0 = sA2[cg * 16 + 2 * j];
        float w1 = sA2[cg * 16 + 2 * j + 1];
#pragma unroll
        for (int r = 0; r < 8; r++) {
            float2 h = unpack2(acc[r * 8 + j]);
            s[r] += fmaxf(h.x, 0.f) * w0 + fmaxf(h.y, 0.f) * w1;
        }
    }
#pragma unroll
    for (int r = 0; r < 8; r++) {
        s[r] += __shfl_xor_sync(0xffffffffu, s[r], 1);
        s[r] += __shfl_xor_sync(0xffffffffu, s[r], 2);
    }

    // weighted scatter: 4 colgroup lanes split the 33 float4 chunks
#pragma unroll 1
    for (int r = 0; r < 8; r++) {
        long rr = base + r;
        if (rr >= NPTS) break;
        int row = (int)rr;
        float sv = s[r] + sb2;
        float a = 1.f / (1.f + expf(-sv));
        int l = lab[row];
        float* arow = g_agg + (size_t)l * 132;
#pragma unroll
        for (int t = 0; t < 8; t++) {
            int kk = cg * 8 + t;
            float4 v = f4[row * 32 + kk];
            red4(arow + kk * 4, v.x * a, v.y * a, v.z * a, v.w * a);
        }
        if (cg == 3) {
            float rx = ctr[l * 3 + 0] - pts[row * 3 + 0];
            float ry = ctr[l * 3 + 1] - pts[row * 3 + 1];
            float rz = ctr[l * 3 + 2] - pts[row * 3 + 2];
            red4(arow + 128, rx * a, ry * a, rz * a, 0.f);
        }
    }
}

// ============ kernel 2: h = relu(agg @ oW1 + ob1) ============
// 256 threads: cg = tid&7 (16 of 128 cols), rg = tid>>3 (8 rows) -> 256 rows/block
__global__ void __launch_bounds__(256) gemmB_kernel(
    const float* __restrict__ oW1, const float* __restrict__ ob1)
{
    // stage weights swizzled [k][q][cg]: 132 rows x 32 u128
    {
        const ulonglong2* wsrc = (const ulonglong2*)oW1;  // 131*32 u128
        for (int idx = threadIdx.x; idx < 131 * 32; idx += 256) {
            int k = idx >> 5, rem = idx & 31;
            int c = rem >> 2, q = rem & 3;
            dynW[k * 32 + q * 8 + c] = wsrc[idx];
        }
        if (threadIdx.x < 32) {
            ulonglong2 z; z.x = 0ull; z.y = 0ull;
            dynW[131 * 32 + threadIdx.x] = z;
        }
    }
    __syncthreads();

    const int tid = threadIdx.x;
    const int cg = tid & 7;
    const int rg = tid >> 3;
    const long base = (long)blockIdx.x * 256 + (long)rg * 8;

    int rowc[8];
#pragma unroll
    for (int r = 0; r < 8; r++) {
        long rr = base + r;
        rowc[r] = (rr < MCLUS) ? (int)rr : (MCLUS - 1);
    }

    u64 acc[64];
    {
        const u64* b2 = (const u64*)ob1;
#pragma unroll
        for (int j = 0; j < 8; j++) {
            u64 bb = __ldg(b2 + cg * 8 + j);
#pragma unroll
            for (int r = 0; r < 8; r++) acc[r * 8 + j] = bb;
        }
    }

    const float4* a4 = (const float4*)g_agg;   // 33 float4 per row
    float4 cur[8], nxt[8];
#pragma unroll
    for (int r = 0; r < 8; r++) cur[r] = a4[rowc[r] * 33];
#pragma unroll 1
    for (int kk = 0; kk < 33; kk++) {
        if (kk < 32) {
#pragma unroll
            for (int r = 0; r < 8; r++) nxt[r] = a4[rowc[r] * 33 + kk + 1];
        }
#pragma unroll
        for (int e = 0; e < 4; e++) {
            const ulonglong2* wp = dynW + (kk * 4 + e) * 32 + cg;
            ulonglong2 wa = wp[0], wb = wp[8], wc = wp[16], wd = wp[24];
            u64 wv[8] = {wa.x, wa.y, wb.x, wb.y, wc.x, wc.y, wd.x, wd.y};
#pragma unroll
            for (int r = 0; r < 8; r++) {
                float4 c4 = cur[r];
                float ae = (e == 0) ? c4.x : (e == 1) ? c4.y : (e == 2) ? c4.z : c4.w;
                u64 tp = pack2(ae, ae);
#pragma unroll
                for (int j = 0; j < 8; j++)
                    acc[r * 8 + j] = fma2(tp, wv[j], acc[r * 8 + j]);
            }
        }
#pragma unroll
        for (int r = 0; r < 8; r++) cur[r] = nxt[r];
    }

#pragma unroll
    for (int r = 0; r < 8; r++) {
        long rr = base + r;
        if (rr < MCLUS) {
            float2* hp = (float2*)(g_h + (size_t)rr * 128 + cg * 16);
#pragma unroll
            for (int j = 0; j < 8; j++) {
                float2 v = unpack2(acc[r * 8 + j]);
                v.x = fmaxf(v.x, 0.f);
                v.y = fmaxf(v.y, 0.f);
                hp[j] = v;
            }
        }
    }
}

// ============ kernel 3: out = relu(h @ oW2 + ob2) ============
// persistent: grid 148, 256 threads: cg = tid&15 (16 of 256 cols), rg = tid>>4 (8 rows)
__global__ void __launch_bounds__(256) gemmC_kernel(
    const float* __restrict__ oW2, const float* __restrict__ ob2,
    float* __restrict__ out)
{
    {
        const ulonglong2* wsrc = (const ulonglong2*)oW2;  // 128*64 u128
        for (int idx = threadIdx.x; idx < 128 * 64; idx += 256) {
            int k = idx >> 6, rem = idx & 63;
            int c = rem >> 2, q = rem & 3;
            dynW[k * 64 + q * 16 + c] = wsrc[idx];
        }
    }
    __syncthreads();

    const int tid = threadIdx.x;
    const int cg = tid & 15;
    const int rg = tid >> 4;
    const int NT = (MCLUS + 127) / 128;   // 391 tiles of 128 rows

    for (int tile = blockIdx.x; tile < NT; tile += gridDim.x) {
        int base = tile * 128 + rg * 8;
        int rowc[8];
#pragma unroll
        for (int r = 0; r < 8; r++) {
            int rr = base + r;
            rowc[r] = (rr < MCLUS) ? rr : (MCLUS - 1);
        }

        u64 acc[64];
        {
            const u64* b2 = (const u64*)ob2;
#pragma unroll
            for (int j = 0; j < 8; j++) {
                u64 bb = __ldg(b2 + cg * 8 + j);
#pragma unroll
                for (int r = 0; r < 8; r++) acc[r * 8 + j] = bb;
            }
        }

        const float4* h4 = (const float4*)g_h;   // 32 float4 per row
        float4 cur[8], nxt[8];
#pragma unroll
        for (int r = 0; r < 8; r++) cur[r] = h4[rowc[r] * 32];
#pragma unroll 1
        for (int kk = 0; kk < 32; kk++) {
            if (kk < 31) {
#pragma unroll
                for (int r = 0; r < 8; r++) nxt[r] = h4[rowc[r] * 32 + kk + 1];
            }
#pragma unroll
            for (int e = 0; e < 4; e++) {
                const ulonglong2* wp = dynW + (kk * 4 + e) * 64 + cg;
                ulonglong2 wa = wp[0], wb = wp[16], wc = wp[32], wd = wp[48];
                u64 wv[8] = {wa.x, wa.y, wb.x, wb.y, wc.x, wc.y, wd.x, wd.y};
#pragma unroll
                for (int r = 0; r < 8; r++) {
                    float4 c4 = cur[r];
                    float ae = (e == 0) ? c4.x : (e == 1) ? c4.y : (e == 2) ? c4.z : c4.w;
                    u64 tp = pack2(ae, ae);
#pragma unroll
                    for (int j = 0; j < 8; j++)
                        acc[r * 8 + j] = fma2(tp, wv[j], acc[r * 8 + j]);
                }
            }
#pragma unroll
            for (int r = 0; r < 8; r++) cur[r] = nxt[r];
        }

#pragma unroll
        for (int r = 0; r < 8; r++) {
            int rr = base + r;
            if (rr < MCLUS) {
                float2* op = (float2*)(out + (size_t)rr * 256 + cg * 16);
#pragma unroll
                for (int j = 0; j < 8; j++) {
                    float2 v = unpack2(acc[r * 8 + j]);
                    v.x = fmaxf(v.x, 0.f);
                    v.y = fmaxf(v.y, 0.f);
                    op[j] = v;
                }
            }
        }
    }
}

extern "C" void kernel_launch(void* const* d_in, const int* in_sizes, int n_in,
                              void* d_out, int out_size) {
    const float* feat = (const float*)d_in[0];
    const float* pts  = (const float*)d_in[1];
    const float* ctr  = (const float*)d_in[2];
    const int*   lab  = (const int*)d_in[3];
    const float* aW1  = (const float*)d_in[4];
    const float* ab1  = (const float*)d_in[5];
    const float* aW2  = (const float*)d_in[6];
    const float* ab2  = (const float*)d_in[7];
    const float* oW1  = (const float*)d_in[8];
    const float* ob1  = (const float*)d_in[9];
    const float* oW2  = (const float*)d_in[10];
    const float* ob2  = (const float*)d_in[11];
    float* out = (float*)d_out;

    static int inited = 0;
    if (!inited) {
        cudaFuncSetAttribute(gemmB_kernel, cudaFuncAttributeMaxDynamicSharedMemorySize, 132 * 32 * 16);
        cudaFuncSetAttribute(gemmC_kernel, cudaFuncAttributeMaxDynamicSharedMemorySize, 128 * 64 * 16);
        inited = 1;
    }

    zero_agg_kernel<<<1024, 256>>>();
    att_scatter_kernel<<<(NPTS + 511) / 512, 256>>>(feat, pts, ctr, lab,
                                                    aW1, ab1, aW2, ab2);
    gemmB_kernel<<<(MCLUS + 255) / 256, 256, 132 * 32 * 16>>>(oW1, ob1);
    gemmC_kernel<<<148, 256, 128 * 64 * 16>>>(oW2, ob2, out);
}

// round 3
// speedup vs baseline: 2.7898x; 1.0606x over previous
#include <cuda_runtime.h>
#include <math.h>

#define NPTS   500000
#define MCLUS  50000

typedef unsigned long long u64;

__device__ float g_agg[(size_t)MCLUS * 132];   // 131 used + 1 pad
__device__ float g_h[(size_t)MCLUS * 128];

// ---------------- packed f32x2 helpers ----------------
__device__ __forceinline__ u64 pack2(float lo, float hi) {
    u64 r;
    asm("mov.b64 %0, {%1,%2};" : "=l"(r) : "f"(lo), "f"(hi));
    return r;
}
__device__ __forceinline__ u64 fma2(u64 a, u64 b, u64 c) {
    u64 d;
    asm("fma.rn.f32x2 %0, %1, %2, %3;" : "=l"(d) : "l"(a), "l"(b), "l"(c));
    return d;
}
__device__ __forceinline__ float2 unpack2(u64 v) {
    float2 f;
    asm("mov.b64 {%0,%1}, %2;" : "=f"(f.x), "=f"(f.y) : "l"(v));
    return f;
}
__device__ __forceinline__ void red4(float* addr, float a, float b, float c, float d) {
    asm volatile("red.global.add.v4.f32 [%0], {%1,%2,%3,%4};"
                 :: "l"(addr), "f"(a), "f"(b), "f"(c), "f"(d) : "memory");
}
__device__ __forceinline__ float elem4(float4 v, int e) {
    return (e == 0) ? v.x : (e == 1) ? v.y : (e == 2) ? v.z : v.w;
}

// ---------------- kernel 0: zero agg ----------------
__global__ void zero_agg_kernel() {
    const size_t total4 = (size_t)MCLUS * 132 / 4;
    float4* p = (float4*)g_agg;
    float4 z = make_float4(0.f, 0.f, 0.f, 0.f);
    for (size_t i = blockIdx.x * blockDim.x + threadIdx.x; i < total4;
         i += (size_t)gridDim.x * blockDim.x)
        p[i] = z;
}

// ============ kernel 1: attention MLP + weighted scatter ============
// 256 thr: cg = tid&3 (16 of 64 cols), rg = tid>>2 (4 rows) -> 256 rows/block
__global__ void __launch_bounds__(256, 2) att_scatter_kernel(
    const float* __restrict__ feat, const float* __restrict__ pts,
    const float* __restrict__ ctr, const int* __restrict__ lab,
    const float* __restrict__ aW1, const float* __restrict__ ab1,
    const float* __restrict__ aW2, const float* __restrict__ ab2)
{
    __shared__ ulonglong2 sW[131 * 16];   // [k][q][cg], 33.5KB
    __shared__ float sB1[64];
    __shared__ float sA2[64];
    __shared__ float sb2;

    {
        const ulonglong2* wsrc = (const ulonglong2*)aW1;   // 131*16 u128
        for (int idx = threadIdx.x; idx < 131 * 16; idx += 256) {
            int k = idx >> 4, c = idx & 15;
            sW[k * 16 + (c & 3) * 4 + (c >> 2)] = wsrc[idx];
        }
        if (threadIdx.x < 64) {
            sB1[threadIdx.x] = ab1[threadIdx.x];
            sA2[threadIdx.x] = aW2[threadIdx.x];
        }
        if (threadIdx.x == 0) sb2 = ab2[0];
    }
    __syncthreads();

    const int cg = threadIdx.x & 3;
    const int rg = threadIdx.x >> 2;
    const int base = blockIdx.x * 256 + rg * 4;

    int rowc[4];
#pragma unroll
    for (int r = 0; r < 4; r++) {
        int rr = base + r;
        rowc[r] = (rr < NPTS) ? rr : (NPTS - 1);
    }

    u64 acc[32];
    {
        const u64* b2 = (const u64*)sB1;
#pragma unroll
        for (int j = 0; j < 8; j++) {
            u64 bb = b2[cg * 8 + j];
#pragma unroll
            for (int r = 0; r < 4; r++) acc[r * 8 + j] = bb;
        }
    }

    // main loop over 128 feature dims (32 float4 chunks) with prefetch
    const float4* f4 = (const float4*)feat;
    float4 cur[4], nxt[4];
#pragma unroll
    for (int r = 0; r < 4; r++) cur[r] = f4[(size_t)rowc[r] * 32];
#pragma unroll 1
    for (int kk = 0; kk < 32; kk++) {
        if (kk < 31) {
#pragma unroll
            for (int r = 0; r < 4; r++) nxt[r] = f4[(size_t)rowc[r] * 32 + kk + 1];
        }
#pragma unroll
        for (int e = 0; e < 4; e++) {
            const ulonglong2* wp = sW + (kk * 4 + e) * 16 + cg;
            ulonglong2 wa = wp[0], wb = wp[4], wc = wp[8], wd = wp[12];
            u64 wv[8] = {wa.x, wa.y, wb.x, wb.y, wc.x, wc.y, wd.x, wd.y};
#pragma unroll
            for (int r = 0; r < 4; r++) {
                float ae = elem4(cur[r], e);
                u64 tp = pack2(ae, ae);
#pragma unroll
                for (int j = 0; j < 8; j++)
                    acc[r * 8 + j] = fma2(tp, wv[j], acc[r * 8 + j]);
            }
        }
#pragma unroll
        for (int r = 0; r < 4; r++) cur[r] = nxt[r];
    }

    // rel-coord dims k = 128..130 (after main loop to reduce live regs)
#pragma unroll
    for (int e = 0; e < 3; e++) {
        const ulonglong2* wp = sW + (128 + e) * 16 + cg;
        ulonglong2 wa = wp[0], wb = wp[4], wc = wp[8], wd = wp[12];
        u64 wv[8] = {wa.x, wa.y, wb.x, wb.y, wc.x, wc.y, wd.x, wd.y};
#pragma unroll
        for (int r = 0; r < 4; r++) {
            int row = rowc[r];
            int l = lab[row];
            float rv = ctr[l * 3 + e] - pts[row * 3 + e];
            u64 tp = pack2(rv, rv);
#pragma unroll
            for (int j = 0; j < 8; j++)
                acc[r * 8 + j] = fma2(tp, wv[j], acc[r * 8 + j]);
        }
    }

    // relu + partial dot with aW2, reduce across 4 colgroup lanes
    float s[4] = {0.f, 0.f, 0.f, 0.f};
#pragma unroll
    for (int j = 0; j < 8; j++) {
        float w0 = sA2[cg * 16 + 2 * j];
        float w1 = sA2[cg * 16 + 2 * j + 1];
#pragma unroll
        for (int r = 0; r < 4; r++) {
            float2 h = unpack2(acc[r * 8 + j]);
            s[r] += fmaxf(h.x, 0.f) * w0 + fmaxf(h.y, 0.f) * w1;
        }
    }
#pragma unroll
    for (int r = 0; r < 4; r++) {
        s[r] += __shfl_xor_sync(0xffffffffu, s[r], 1);
        s[r] += __shfl_xor_sync(0xffffffffu, s[r], 2);
    }

    // weighted scatter: 4 cg lanes split 32 float4 chunks; cg==3 adds rel chunk
#pragma unroll 1
    for (int r = 0; r < 4; r++) {
        int row = base + r;
        if (row >= NPTS) break;
        float a = 1.f / (1.f + expf(-(s[r] + sb2)));
        int l = lab[row];
        float* arow = g_agg + (size_t)l * 132;
#pragma unroll
        for (int t = 0; t < 8; t++) {
            int kk = cg * 8 + t;
            float4 v = f4[(size_t)row * 32 + kk];
            red4(arow + kk * 4, v.x * a, v.y * a, v.z * a, v.w * a);
        }
        if (cg == 3) {
            float rx = ctr[l * 3 + 0] - pts[row * 3 + 0];
            float ry = ctr[l * 3 + 1] - pts[row * 3 + 1];
            float rz = ctr[l * 3 + 2] - pts[row * 3 + 2];
            red4(arow + 128, rx * a, ry * a, rz * a, 0.f);
        }
    }
}

// ============ kernel 2: h = relu(agg @ oW1 + ob1) ============
// grid (196, 2): y = 64-col slice. 256 thr: cg = tid&3, rg = tid>>2, 4 rows.
__global__ void __launch_bounds__(256, 2) gemmB_kernel(
    const float* __restrict__ oW1, const float* __restrict__ ob1)
{
    __shared__ ulonglong2 sW[132 * 16];   // 33.8KB
    const int slice = blockIdx.y;
    {
        const ulonglong2* wsrc = (const ulonglong2*)oW1;  // 131 x 32 u128
        for (int idx = threadIdx.x; idx < 131 * 16; idx += 256) {
            int k = idx >> 4, c = idx & 15;
            sW[k * 16 + (c & 3) * 4 + (c >> 2)] = wsrc[k * 32 + slice * 16 + c];
        }
        if (threadIdx.x < 16) {
            ulonglong2 z; z.x = 0ull; z.y = 0ull;
            sW[131 * 16 + threadIdx.x] = z;
        }
    }
    __syncthreads();

    const int cg = threadIdx.x & 3;
    const int rg = threadIdx.x >> 2;
    const int base = blockIdx.x * 256 + rg * 4;

    int rowc[4];
#pragma unroll
    for (int r = 0; r < 4; r++) {
        int rr = base + r;
        rowc[r] = (rr < MCLUS) ? rr : (MCLUS - 1);
    }

    u64 acc[32];
    {
        const u64* b2 = (const u64*)ob1;
#pragma unroll
        for (int j = 0; j < 8; j++) {
            u64 bb = __ldg(b2 + slice * 32 + cg * 8 + j);
#pragma unroll
            for (int r = 0; r < 4; r++) acc[r * 8 + j] = bb;
        }
    }

    const float4* a4 = (const float4*)g_agg;   // 33 float4 per row
    float4 cur[4], nxt[4];
#pragma unroll
    for (int r = 0; r < 4; r++) cur[r] = a4[(size_t)rowc[r] * 33];
#pragma unroll 1
    for (int kk = 0; kk < 33; kk++) {
        if (kk < 32) {
#pragma unroll
            for (int r = 0; r < 4; r++) nxt[r] = a4[(size_t)rowc[r] * 33 + kk + 1];
        }
#pragma unroll
        for (int e = 0; e < 4; e++) {
            const ulonglong2* wp = sW + (kk * 4 + e) * 16 + cg;
            ulonglong2 wa = wp[0], wb = wp[4], wc = wp[8], wd = wp[12];
            u64 wv[8] = {wa.x, wa.y, wb.x, wb.y, wc.x, wc.y, wd.x, wd.y};
#pragma unroll
            for (int r = 0; r < 4; r++) {
                float ae = elem4(cur[r], e);
                u64 tp = pack2(ae, ae);
#pragma unroll
                for (int j = 0; j < 8; j++)
                    acc[r * 8 + j] = fma2(tp, wv[j], acc[r * 8 + j]);
            }
        }
#pragma unroll
        for (int r = 0; r < 4; r++) cur[r] = nxt[r];
    }

#pragma unroll
    for (int r = 0; r < 4; r++) {
        int rr = base + r;
        if (rr < MCLUS) {
            float2* hp = (float2*)(g_h + (size_t)rr * 128 + slice * 64 + cg * 16);
#pragma unroll
            for (int j = 0; j < 8; j++) {
                float2 v = unpack2(acc[r * 8 + j]);
                v.x = fmaxf(v.x, 0.f);
                v.y = fmaxf(v.y, 0.f);
                hp[j] = v;
            }
        }
    }
}

// ============ kernel 3: out = relu(h @ oW2 + ob2) ============
// grid (196, 4): y = 64-col slice.
__global__ void __launch_bounds__(256, 2) gemmC_kernel(
    const float* __restrict__ oW2, const float* __restrict__ ob2,
    float* __restrict__ out)
{
    __shared__ ulonglong2 sW[128 * 16];   // 32.8KB
    const int slice = blockIdx.y;
    {
        const ulonglong2* wsrc = (const ulonglong2*)oW2;  // 128 x 64 u128
        for (int idx = threadIdx.x; idx < 128 * 16; idx += 256) {
            int k = idx >> 4, c = idx & 15;
            sW[k * 16 + (c & 3) * 4 + (c >> 2)] = wsrc[k * 64 + slice * 16 + c];
        }
    }
    __syncthreads();

    const int cg = threadIdx.x & 3;
    const int rg = threadIdx.x >> 2;
    const int base = blockIdx.x * 256 + rg * 4;

    int rowc[4];
#pragma unroll
    for (int r = 0; r < 4; r++) {
        int rr = base + r;
        rowc[r] = (rr < MCLUS) ? rr : (MCLUS - 1);
    }

    u64 acc[32];
    {
        const u64* b2 = (const u64*)ob2;
#pragma unroll
        for (int j = 0; j < 8; j++) {
            u64 bb = __ldg(b2 + slice * 32 + cg * 8 + j);
#pragma unroll
            for (int r = 0; r < 4; r++) acc[r * 8 + j] = bb;
        }
    }

    const float4* h4 = (const float4*)g_h;   // 32 float4 per row
    float4 cur[4], nxt[4];
#pragma unroll
    for (int r = 0; r < 4; r++) cur[r] = h4[(size_t)rowc[r] * 32];
#pragma unroll 1
    for (int kk = 0; kk < 32; kk++) {
        if (kk < 31) {
#pragma unroll
            for (int r = 0; r < 4; r++) nxt[r] = h4[(size_t)rowc[r] * 32 + kk + 1];
        }
#pragma unroll
        for (int e = 0; e < 4; e++) {
            const ulonglong2* wp = sW + (kk * 4 + e) * 16 + cg;
            ulonglong2 wa = wp[0], wb = wp[4], wc = wp[8], wd = wp[12];
            u64 wv[8] = {wa.x, wa.y, wb.x, wb.y, wc.x, wc.y, wd.x, wd.y};
#pragma unroll
            for (int r = 0; r < 4; r++) {
                float ae = elem4(cur[r], e);
                u64 tp = pack2(ae, ae);
#pragma unroll
                for (int j = 0; j < 8; j++)
                    acc[r * 8 + j] = fma2(tp, wv[j], acc[r * 8 + j]);
            }
        }
#pragma unroll
        for (int r = 0; r < 4; r++) cur[r] = nxt[r];
    }

#pragma unroll
    for (int r = 0; r < 4; r++) {
        int rr = base + r;
        if (rr < MCLUS) {
            float2* op = (float2*)(out + (size_t)rr * 256 + slice * 64 + cg * 16);
#pragma unroll
            for (int j = 0; j < 8; j++) {
                float2 v = unpack2(acc[r * 8 + j]);
                v.x = fmaxf(v.x, 0.f);
                v.y = fmaxf(v.y, 0.f);
                op[j] = v;
            }
        }
    }
}

extern "C" void kernel_launch(void* const* d_in, const int* in_sizes, int n_in,
                              void* d_out, int out_size) {
    const float* feat = (const float*)d_in[0];
    const float* pts  = (const float*)d_in[1];
    const float* ctr  = (const float*)d_in[2];
    const int*   lab  = (const int*)d_in[3];
    const float* aW1  = (const float*)d_in[4];
    const float* ab1  = (const float*)d_in[5];
    const float* aW2  = (const float*)d_in[6];
    const float* ab2  = (const float*)d_in[7];
    const float* oW1  = (const float*)d_in[8];
    const float* ob1  = (const float*)d_in[9];
    const float* oW2  = (const float*)d_in[10];
    const float* ob2  = (const float*)d_in[11];
    float* out = (float*)d_out;

    zero_agg_kernel<<<2048, 256>>>();
    att_scatter_kernel<<<(NPTS + 255) / 256, 256>>>(feat, pts, ctr, lab,
                                                    aW1, ab1, aW2, ab2);
    gemmB_kernel<<<dim3((MCLUS + 255) / 256, 2), 256>>>(oW1, ob1);
    gemmC_kernel<<<dim3((MCLUS + 255) / 256, 4), 256>>>(oW2, ob2, out);
}

// round 4
// speedup vs baseline: 3.4485x; 1.2361x over previous
#include <cuda_runtime.h>
#include <math.h>

#define NPTS   500000
#define MCLUS  50000

typedef unsigned long long u64;

__device__ float g_agg[(size_t)MCLUS * 132];   // 131 used + 1 pad
__device__ float g_h[(size_t)MCLUS * 128];

// ---------------- helpers ----------------
__device__ __forceinline__ u64 pack2(float lo, float hi) {
    u64 r;
    asm("mov.b64 %0, {%1,%2};" : "=l"(r) : "f"(lo), "f"(hi));
    return r;
}
__device__ __forceinline__ u64 fma2(u64 a, u64 b, u64 c) {
    u64 d;
    asm("fma.rn.f32x2 %0, %1, %2, %3;" : "=l"(d) : "l"(a), "l"(b), "l"(c));
    return d;
}
__device__ __forceinline__ float2 unpack2(u64 v) {
    float2 f;
    asm("mov.b64 {%0,%1}, %2;" : "=f"(f.x), "=f"(f.y) : "l"(v));
    return f;
}
__device__ __forceinline__ void red4(float* addr, float a, float b, float c, float d) {
    asm volatile("red.global.add.v4.f32 [%0], {%1,%2,%3,%4};"
                 :: "l"(addr), "f"(a), "f"(b), "f"(c), "f"(d) : "memory");
}
__device__ __forceinline__ float elem4(float4 v, int e) {
    return (e == 0) ? v.x : (e == 1) ? v.y : (e == 2) ? v.z : v.w;
}
__device__ __forceinline__ void cpasync16(void* smem_dst, const void* gsrc) {
    unsigned saddr = (unsigned)__cvta_generic_to_shared(smem_dst);
    asm volatile("cp.async.ca.shared.global [%0], [%1], 16;" :: "r"(saddr), "l"(gsrc));
}
__device__ __forceinline__ void cp_commit() { asm volatile("cp.async.commit_group;"); }
__device__ __forceinline__ void cp_wait0()  { asm volatile("cp.async.wait_group 0;" ::: "memory"); }

#define ACT_STRIDE 5           // float4 per row in act buffer (conflict-free)
#define ACT_BUF    (256 * ACT_STRIDE)   // float4 per buffer

// ---------------- kernel 0: zero agg ----------------
__global__ void zero_agg_kernel() {
    const size_t total4 = (size_t)MCLUS * 132 / 4;
    float4* p = (float4*)g_agg;
    float4 z = make_float4(0.f, 0.f, 0.f, 0.f);
    for (size_t i = blockIdx.x * blockDim.x + threadIdx.x; i < total4;
         i += (size_t)gridDim.x * blockDim.x)
        p[i] = z;
}

// ============ kernel 1: attention MLP + weighted scatter ============
// 256 thr: cg = tid&3 (16 of 64 cols), rg = tid>>2; thread rows = rg + r*64.
__global__ void __launch_bounds__(256, 2) att_scatter_kernel(
    const float* __restrict__ feat, const float* __restrict__ pts,
    const float* __restrict__ ctr, const int* __restrict__ lab,
    const float* __restrict__ aW1, const float* __restrict__ ab1,
    const float* __restrict__ aW2, const float* __restrict__ ab2)
{
    extern __shared__ char dynRaw[];
    ulonglong2* sW  = (ulonglong2*)dynRaw;                       // 131*16
    float4*    sAct = (float4*)(dynRaw + 131 * 16 * 16);         // 2 * ACT_BUF
    float*     sB1  = (float*)(dynRaw + 131 * 16 * 16 + 2 * ACT_BUF * 16);
    float*     sA2  = sB1 + 64;
    float*     sRel = sA2 + 64;          // 256*3
    float*     sAtt = sRel + 768;        // 256
    int*       sLab = (int*)(sAtt + 256);
    float*     sb2p = (float*)(sLab + 256);

    const int tid = threadIdx.x;
    const int gbase = blockIdx.x * 256;
    const float4* f4 = (const float4*)feat;

    // stage weights swizzled [k][q][cg]
    {
        const ulonglong2* wsrc = (const ulonglong2*)aW1;
        for (int idx = tid; idx < 131 * 16; idx += 256) {
            int k = idx >> 4, c = idx & 15;
            sW[k * 16 + (c & 3) * 4 + (c >> 2)] = wsrc[idx];
        }
        if (tid < 64) { sB1[tid] = ab1[tid]; sA2[tid] = aW2[tid]; }
        if (tid == 0) *sb2p = ab2[0];
        int row = gbase + tid;
        int rc = (row < NPTS) ? row : (NPTS - 1);
        int l = lab[rc];
        sLab[tid] = l;
        sRel[tid * 3 + 0] = ctr[l * 3 + 0] - pts[rc * 3 + 0];
        sRel[tid * 3 + 1] = ctr[l * 3 + 1] - pts[rc * 3 + 1];
        sRel[tid * 3 + 2] = ctr[l * 3 + 2] - pts[rc * 3 + 2];
    }

    // issue chunk 0
    {
        for (int idx = tid; idx < 256 * 4; idx += 256) {
            int row = idx >> 2, c4 = idx & 3;
            int gr = gbase + row; if (gr >= NPTS) gr = NPTS - 1;
            cpasync16(&sAct[row * ACT_STRIDE + c4], f4 + (size_t)gr * 32 + c4);
        }
        cp_commit();
    }
    __syncthreads();   // weights/rel ready

    const int cg = tid & 3;
    const int rg = tid >> 2;

    u64 acc[32];
    {
        const u64* b2 = (const u64*)sB1;
#pragma unroll
        for (int j = 0; j < 8; j++) {
            u64 bb = b2[cg * 8 + j];
#pragma unroll
            for (int r = 0; r < 4; r++) acc[r * 8 + j] = bb;
        }
    }

#pragma unroll 1
    for (int c = 0; c < 8; c++) {
        cp_wait0();
        __syncthreads();
        if (c < 7) {
            float4* dst = sAct + ((c + 1) & 1) * ACT_BUF;
            for (int idx = tid; idx < 256 * 4; idx += 256) {
                int row = idx >> 2, c4 = idx & 3;
                int gr = gbase + row; if (gr >= NPTS) gr = NPTS - 1;
                cpasync16(&dst[row * ACT_STRIDE + c4], f4 + (size_t)gr * 32 + (c + 1) * 4 + c4);
            }
            cp_commit();
        }
        const float4* A = sAct + (c & 1) * ACT_BUF;
#pragma unroll
        for (int k4 = 0; k4 < 4; k4++) {
            float4 av[4];
#pragma unroll
            for (int r = 0; r < 4; r++) av[r] = A[(rg + r * 64) * ACT_STRIDE + k4];
#pragma unroll
            for (int e = 0; e < 4; e++) {
                const ulonglong2* wp = sW + (c * 16 + k4 * 4 + e) * 16 + cg;
                ulonglong2 wa = wp[0], wb = wp[4], wc = wp[8], wd = wp[12];
                u64 wv[8] = {wa.x, wa.y, wb.x, wb.y, wc.x, wc.y, wd.x, wd.y};
#pragma unroll
                for (int r = 0; r < 4; r++) {
                    float ae = elem4(av[r], e);
                    u64 tp = pack2(ae, ae);
#pragma unroll
                    for (int j = 0; j < 8; j++)
                        acc[r * 8 + j] = fma2(tp, wv[j], acc[r * 8 + j]);
                }
            }
        }
    }

    // rel-coord dims k = 128..130
#pragma unroll
    for (int e = 0; e < 3; e++) {
        const ulonglong2* wp = sW + (128 + e) * 16 + cg;
        ulonglong2 wa = wp[0], wb = wp[4], wc = wp[8], wd = wp[12];
        u64 wv[8] = {wa.x, wa.y, wb.x, wb.y, wc.x, wc.y, wd.x, wd.y};
#pragma unroll
        for (int r = 0; r < 4; r++) {
            float rv = sRel[(rg + r * 64) * 3 + e];
            u64 tp = pack2(rv, rv);
#pragma unroll
            for (int j = 0; j < 8; j++)
                acc[r * 8 + j] = fma2(tp, wv[j], acc[r * 8 + j]);
        }
    }

    // relu + dot aW2, reduce over cg lanes, sigmoid -> sAtt
    {
        float s[4] = {0.f, 0.f, 0.f, 0.f};
#pragma unroll
        for (int j = 0; j < 8; j++) {
            float w0 = sA2[cg * 16 + 2 * j];
            float w1 = sA2[cg * 16 + 2 * j + 1];
#pragma unroll
            for (int r = 0; r < 4; r++) {
                float2 h = unpack2(acc[r * 8 + j]);
                s[r] += fmaxf(h.x, 0.f) * w0 + fmaxf(h.y, 0.f) * w1;
            }
        }
        float b2v = *sb2p;
#pragma unroll
        for (int r = 0; r < 4; r++) {
            s[r] += __shfl_xor_sync(0xffffffffu, s[r], 1);
            s[r] += __shfl_xor_sync(0xffffffffu, s[r], 2);
            if (cg == 0)
                sAtt[rg + r * 64] = 1.f / (1.f + expf(-(s[r] + b2v)));
        }
    }
    __syncthreads();

    // scatter phase: restage feat chunks coalesced, red4 from smem
    {
        for (int idx = tid; idx < 256 * 4; idx += 256) {
            int row = idx >> 2, c4 = idx & 3;
            int gr = gbase + row; if (gr >= NPTS) gr = NPTS - 1;
            cpasync16(&sAct[row * ACT_STRIDE + c4], f4 + (size_t)gr * 32 + c4);
        }
        cp_commit();
    }
#pragma unroll 1
    for (int c = 0; c < 8; c++) {
        cp_wait0();
        __syncthreads();
        if (c < 7) {
            float4* dst = sAct + ((c + 1) & 1) * ACT_BUF;
            for (int idx = tid; idx < 256 * 4; idx += 256) {
                int row = idx >> 2, c4 = idx & 3;
                int gr = gbase + row; if (gr >= NPTS) gr = NPTS - 1;
                cpasync16(&dst[row * ACT_STRIDE + c4], f4 + (size_t)gr * 32 + (c + 1) * 4 + c4);
            }
            cp_commit();
        }
        const float4* A = sAct + (c & 1) * ACT_BUF;
#pragma unroll
        for (int r = 0; r < 4; r++) {
            int rl = rg + r * 64;
            int row = gbase + rl;
            if (row < NPTS) {
                float a = sAtt[rl];
                int l = sLab[rl];
                float4 v = A[rl * ACT_STRIDE + cg];
                red4(g_agg + (size_t)l * 132 + (c * 4 + cg) * 4,
                     v.x * a, v.y * a, v.z * a, v.w * a);
            }
        }
    }
    if (cg == 0) {
#pragma unroll
        for (int r = 0; r < 4; r++) {
            int rl = rg + r * 64;
            int row = gbase + rl;
            if (row < NPTS) {
                float a = sAtt[rl];
                int l = sLab[rl];
                red4(g_agg + (size_t)l * 132 + 128,
                     sRel[rl * 3 + 0] * a, sRel[rl * 3 + 1] * a,
                     sRel[rl * 3 + 2] * a, 0.f);
            }
        }
    }
}

// ============ kernel 2: h = relu(agg @ oW1 + ob1) ============
// grid (196, 2): y = 64-col slice.
__global__ void __launch_bounds__(256, 2) gemmB_kernel(
    const float* __restrict__ oW1, const float* __restrict__ ob1)
{
    extern __shared__ char dynRaw[];
    ulonglong2* sW  = (ulonglong2*)dynRaw;                 // 131*16
    float4*    sAct = (float4*)(dynRaw + 131 * 16 * 16);   // 2 * ACT_BUF

    const int tid = threadIdx.x;
    const int slice = blockIdx.y;
    const int gbase = blockIdx.x * 256;
    const float4* a4 = (const float4*)g_agg;   // 33 f4 per row

    {
        const ulonglong2* wsrc = (const ulonglong2*)oW1;   // 131 x 32
        for (int idx = tid; idx < 131 * 16; idx += 256) {
            int k = idx >> 4, c = idx & 15;
            sW[k * 16 + (c & 3) * 4 + (c >> 2)] = wsrc[k * 32 + slice * 16 + c];
        }
    }
    {
        for (int idx = tid; idx < 256 * 4; idx += 256) {
            int row = idx >> 2, c4 = idx & 3;
            int gr = gbase + row; if (gr >= MCLUS) gr = MCLUS - 1;
            cpasync16(&sAct[row * ACT_STRIDE + c4], a4 + (size_t)gr * 33 + c4);
        }
        cp_commit();
    }
    __syncthreads();

    const int cg = tid & 3;
    const int rg = tid >> 2;

    u64 acc[32];
    {
        const u64* b2 = (const u64*)ob1;
#pragma unroll
        for (int j = 0; j < 8; j++) {
            u64 bb = __ldg(b2 + slice * 32 + cg * 8 + j);
#pragma unroll
            for (int r = 0; r < 4; r++) acc[r * 8 + j] = bb;
        }
    }

#pragma unroll 1
    for (int c = 0; c < 8; c++) {
        cp_wait0();
        __syncthreads();
        if (c < 7) {
            float4* dst = sAct + ((c + 1) & 1) * ACT_BUF;
            for (int idx = tid; idx < 256 * 4; idx += 256) {
                int row = idx >> 2, c4 = idx & 3;
                int gr = gbase + row; if (gr >= MCLUS) gr = MCLUS - 1;
                cpasync16(&dst[row * ACT_STRIDE + c4], a4 + (size_t)gr * 33 + (c + 1) * 4 + c4);
            }
            cp_commit();
        }
        const float4* A = sAct + (c & 1) * ACT_BUF;
#pragma unroll
        for (int k4 = 0; k4 < 4; k4++) {
            float4 av[4];
#pragma unroll
            for (int r = 0; r < 4; r++) av[r] = A[(rg + r * 64) * ACT_STRIDE + k4];
#pragma unroll
            for (int e = 0; e < 4; e++) {
                const ulonglong2* wp = sW + (c * 16 + k4 * 4 + e) * 16 + cg;
                ulonglong2 wa = wp[0], wb = wp[4], wc = wp[8], wd = wp[12];
                u64 wv[8] = {wa.x, wa.y, wb.x, wb.y, wc.x, wc.y, wd.x, wd.y};
#pragma unroll
                for (int r = 0; r < 4; r++) {
                    float ae = elem4(av[r], e);
                    u64 tp = pack2(ae, ae);
#pragma unroll
                    for (int j = 0; j < 8; j++)
                        acc[r * 8 + j] = fma2(tp, wv[j], acc[r * 8 + j]);
                }
            }
        }
    }

    // tail k = 128..130 (k=131 is zero pad in agg; skip)
    {
        float4 tv[4];
#pragma unroll
        for (int r = 0; r < 4; r++) {
            int gr = gbase + rg + r * 64; if (gr >= MCLUS) gr = MCLUS - 1;
            tv[r] = a4[(size_t)gr * 33 + 32];
        }
#pragma unroll
        for (int e = 0; e < 3; e++) {
            const ulonglong2* wp = sW + (128 + e) * 16 + cg;
            ulonglong2 wa = wp[0], wb = wp[4], wc = wp[8], wd = wp[12];
            u64 wv[8] = {wa.x, wa.y, wb.x, wb.y, wc.x, wc.y, wd.x, wd.y};
#pragma unroll
            for (int r = 0; r < 4; r++) {
                float ae = elem4(tv[r], e);
                u64 tp = pack2(ae, ae);
#pragma unroll
                for (int j = 0; j < 8; j++)
                    acc[r * 8 + j] = fma2(tp, wv[j], acc[r * 8 + j]);
            }
        }
    }

#pragma unroll
    for (int r = 0; r < 4; r++) {
        int rr = gbase + rg + r * 64;
        if (rr < MCLUS) {
            float2* hp = (float2*)(g_h + (size_t)rr * 128 + slice * 64 + cg * 16);
#pragma unroll
            for (int j = 0; j < 8; j++) {
                float2 v = unpack2(acc[r * 8 + j]);
                v.x = fmaxf(v.x, 0.f);
                v.y = fmaxf(v.y, 0.f);
                hp[j] = v;
            }
        }
    }
}

// ============ kernel 3: out = relu(h @ oW2 + ob2) ============
// grid (196, 4): y = 64-col slice.
__global__ void __launch_bounds__(256, 2) gemmC_kernel(
    const float* __restrict__ oW2, const float* __restrict__ ob2,
    float* __restrict__ out)
{
    extern __shared__ char dynRaw[];
    ulonglong2* sW  = (ulonglong2*)dynRaw;                 // 128*16
    float4*    sAct = (float4*)(dynRaw + 128 * 16 * 16);   // 2 * ACT_BUF

    const int tid = threadIdx.x;
    const int slice = blockIdx.y;
    const int gbase = blockIdx.x * 256;
    const float4* h4 = (const float4*)g_h;   // 32 f4 per row

    {
        const ulonglong2* wsrc = (const ulonglong2*)oW2;   // 128 x 64
        for (int idx = tid; idx < 128 * 16; idx += 256) {
            int k = idx >> 4, c = idx & 15;
            sW[k * 16 + (c & 3) * 4 + (c >> 2)] = wsrc[k * 64 + slice * 16 + c];
        }
    }
    {
        for (int idx = tid; idx < 256 * 4; idx += 256) {
            int row = idx >> 2, c4 = idx & 3;
            int gr = gbase + row; if (gr >= MCLUS) gr = MCLUS - 1;
            cpasync16(&sAct[row * ACT_STRIDE + c4], h4 + (size_t)gr * 32 + c4);
        }
        cp_commit();
    }
    __syncthreads();

    const int cg = tid & 3;
    const int rg = tid >> 2;

    u64 acc[32];
    {
        const u64* b2 = (const u64*)ob2;
#pragma unroll
        for (int j = 0; j < 8; j++) {
            u64 bb = __ldg(b2 + slice * 32 + cg * 8 + j);
#pragma unroll
            for (int r = 0; r < 4; r++) acc[r * 8 + j] = bb;
        }
    }

#pragma unroll 1
    for (int c = 0; c < 8; c++) {
        cp_wait0();
        __syncthreads();
        if (c < 7) {
            float4* dst = sAct + ((c + 1) & 1) * ACT_BUF;
            for (int idx = tid; idx < 256 * 4; idx += 256) {
                int row = idx >> 2, c4 = idx & 3;
                int gr = gbase + row; if (gr >= MCLUS) gr = MCLUS - 1;
                cpasync16(&dst[row * ACT_STRIDE + c4], h4 + (size_t)gr * 32 + (c + 1) * 4 + c4);
            }
            cp_commit();
        }
        const float4* A = sAct + (c & 1) * ACT_BUF;
#pragma unroll
        for (int k4 = 0; k4 < 4; k4++) {
            float4 av[4];
#pragma unroll
            for (int r = 0; r < 4; r++) av[r] = A[(rg + r * 64) * ACT_STRIDE + k4];
#pragma unroll
            for (int e = 0; e < 4; e++) {
                const ulonglong2* wp = sW + (c * 16 + k4 * 4 + e) * 16 + cg;
                ulonglong2 wa = wp[0], wb = wp[4], wc = wp[8], wd = wp[12];
                u64 wv[8] = {wa.x, wa.y, wb.x, wb.y, wc.x, wc.y, wd.x, wd.y};
#pragma unroll
                for (int r = 0; r < 4; r++) {
                    float ae = elem4(av[r], e);
                    u64 tp = pack2(ae, ae);
#pragma unroll
                    for (int j = 0; j < 8; j++)
                        acc[r * 8 + j] = fma2(tp, wv[j], acc[r * 8 + j]);
                }
            }
        }
    }

#pragma unroll
    for (int r = 0; r < 4; r++) {
        int rr = gbase + rg + r * 64;
        if (rr < MCLUS) {
            float2* op = (float2*)(out + (size_t)rr * 256 + slice * 64 + cg * 16);
#pragma unroll
            for (int j = 0; j < 8; j++) {
                float2 v = unpack2(acc[r * 8 + j]);
                v.x = fmaxf(v.x, 0.f);
                v.y = fmaxf(v.y, 0.f);
                op[j] = v;
            }
        }
    }
}

extern "C" void kernel_launch(void* const* d_in, const int* in_sizes, int n_in,
                              void* d_out, int out_size) {
    const float* feat = (const float*)d_in[0];
    const float* pts  = (const float*)d_in[1];
    const float* ctr  = (const float*)d_in[2];
    const int*   lab  = (const int*)d_in[3];
    const float* aW1  = (const float*)d_in[4];
    const float* ab1  = (const float*)d_in[5];
    const float* aW2  = (const float*)d_in[6];
    const float* ab2  = (const float*)d_in[7];
    const float* oW1  = (const float*)d_in[8];
    const float* ob1  = (const float*)d_in[9];
    const float* oW2  = (const float*)d_in[10];
    const float* ob2  = (const float*)d_in[11];
    float* out = (float*)d_out;

    const int attSmem  = 131 * 16 * 16 + 2 * ACT_BUF * 16 + (64 + 64 + 768 + 256 + 1) * 4 + 256 * 4;
    const int bSmem    = 131 * 16 * 16 + 2 * ACT_BUF * 16;
    const int cSmem    = 128 * 16 * 16 + 2 * ACT_BUF * 16;

    static int inited = 0;
    if (!inited) {
        cudaFuncSetAttribute(att_scatter_kernel, cudaFuncAttributeMaxDynamicSharedMemorySize, attSmem);
        cudaFuncSetAttribute(gemmB_kernel, cudaFuncAttributeMaxDynamicSharedMemorySize, bSmem);
        cudaFuncSetAttribute(gemmC_kernel, cudaFuncAttributeMaxDynamicSharedMemorySize, cSmem);
        inited = 1;
    }

    zero_agg_kernel<<<2048, 256>>>();
    att_scatter_kernel<<<(NPTS + 255) / 256, 256, attSmem>>>(feat, pts, ctr, lab,
                                                             aW1, ab1, aW2, ab2);
    gemmB_kernel<<<dim3((MCLUS + 255) / 256, 2), 256, bSmem>>>(oW1, ob1);
    gemmC_kernel<<<dim3((MCLUS + 255) / 256, 4), 256, cSmem>>>(oW2, ob2, out);
}